// round 11
// baseline (speedup 1.0000x reference)
#include <cuda_runtime.h>
#include <cuda_fp16.h>
#include <cstdint>

// OnlineHadamard round 11: r10 + conflict-free swizzled B layout.
//  B row k (192B): 8 units of 16B at position u' = u ^ ((k>>1)&3).
//  Unit t holds m = {4t..4t+3, 32+4t..32+4t+3}  -> FHT thread writes ONE STS.128.
//  GEMM ldsm applies the same lane-constant swizzle; epilogue remaps m columns.

#define KDIM 172
#define MDIM 64
#define NROW 11008
#define NT 384

#define ASTR 368
#define BSTR 192
#define A_BYTES (176 * ASTR)        // 64768
#define B_BYTES (176 * BSTR)        // 33792 per buffer
#define OFF_B0  (A_BYTES)
#define OFF_B1  (A_BYTES + B_BYTES)
#define SMEM_DYN (A_BYTES + 2 * B_BYTES)   // 132352
#define NQUAD 43

__device__ __forceinline__ uint32_t smem_u32(const void* p) {
    uint32_t a;
    asm("{ .reg .u64 t; cvta.to.shared.u64 t, %1; cvt.u32.u64 %0, t; }" : "=r"(a) : "l"(p));
    return a;
}
__device__ __forceinline__ uint32_t h2_u32(__half2 h) {
    uint32_t u;
    *(__half2*)&u = h;
    return u;
}
__device__ __forceinline__ void ldsm_x4(uint32_t* r, uint32_t addr) {
    asm volatile("ldmatrix.sync.aligned.m8n8.x4.shared.b16 {%0,%1,%2,%3}, [%4];"
                 : "=r"(r[0]), "=r"(r[1]), "=r"(r[2]), "=r"(r[3]) : "r"(addr));
}
__device__ __forceinline__ void ldsm_x4t(uint32_t* r, uint32_t addr) {
    asm volatile("ldmatrix.sync.aligned.m8n8.x4.trans.shared.b16 {%0,%1,%2,%3}, [%4];"
                 : "=r"(r[0]), "=r"(r[1]), "=r"(r[2]), "=r"(r[3]) : "r"(addr));
}
__device__ __forceinline__ void mma_f16(float* c, const uint32_t* a, uint32_t b0, uint32_t b1) {
    asm volatile("mma.sync.aligned.m16n8k16.row.col.f32.f16.f16.f32 "
                 "{%0,%1,%2,%3}, {%4,%5,%6,%7}, {%8,%9}, {%0,%1,%2,%3};"
                 : "+f"(c[0]), "+f"(c[1]), "+f"(c[2]), "+f"(c[3])
                 : "r"(a[0]), "r"(a[1]), "r"(a[2]), "r"(a[3]), "r"(b0), "r"(b1));
}

// FHT64, 8 elems/thread. Writes thread's 8 halves as ONE STS.128 into unit
// tg of chunk c, swizzled by ((c>>1)&3). Conflict-free per 8-lane phase.
__device__ __forceinline__ void bfly8_store(float4 lo, float4 hi, char* bbuf,
                                            int c, int tg, float scale) {
    float v[8] = {lo.x, lo.y, lo.z, lo.w, hi.x, hi.y, hi.z, hi.w};
    float t;
    #pragma unroll
    for (int i = 0; i < 4; i++) { t = v[i]; v[i] = t + v[i+4]; v[i+4] = t - v[i+4]; }
    #pragma unroll
    for (int g2 = 0; g2 < 8; g2 += 2) { t = v[g2]; v[g2] = t + v[g2+1]; v[g2+1] = t - v[g2+1]; }
    #pragma unroll
    for (int b = 0; b < 8; b += 4)
        #pragma unroll
        for (int i = 0; i < 2; i++) {
            t = v[b+i]; v[b+i] = t + v[b+i+2]; v[b+i+2] = t - v[b+i+2];
        }
    #pragma unroll
    for (int s = 1; s <= 4; s <<= 1) {
        bool up = (tg & s) != 0;
        #pragma unroll
        for (int i = 0; i < 8; i++) {
            float q = __shfl_xor_sync(0xffffffffu, v[i], s);
            v[i] = up ? (q - v[i]) : (v[i] + q);
        }
    }
    uint32_t h01 = h2_u32(__floats2half2_rn(v[0]*scale, v[1]*scale));
    uint32_t h23 = h2_u32(__floats2half2_rn(v[2]*scale, v[3]*scale));
    uint32_t h45 = h2_u32(__floats2half2_rn(v[4]*scale, v[5]*scale));
    uint32_t h67 = h2_u32(__floats2half2_rn(v[6]*scale, v[7]*scale));
    int u = tg ^ ((c >> 1) & 3);
    *(uint4*)(bbuf + c * BSTR + u * 16) = make_uint4(h01, h23, h45, h67);
}

__global__ __launch_bounds__(NT, 1)
void onl_had_r11_kernel(const float* __restrict__ x,
                        const float* __restrict__ had,
                        float* __restrict__ out, int rows)
{
    extern __shared__ char sm[];
    const uint32_t sbase = smem_u32(sm);
    const int tid = threadIdx.x, lane = tid & 31, warp = tid >> 5;
    const int tg = lane & 7, g = lane >> 3;

    // ---- one-time: A = had (fp16), zero-padded to 176x176 ----
    for (int idx = tid; idx < 176 * 176; idx += NT) {
        int j = idx / 176, k = idx - j * 176;
        float v = (j < KDIM && k < KDIM) ? had[j * KDIM + k] : 0.0f;
        *(__half*)(sm + j * ASTR + 2 * k) = __float2half_rn(v);
    }
    // zero data region (128B) of B pad rows 172..175, both buffers
    for (int idx = tid; idx < 2 * 4 * 32; idx += NT) {
        int b = idx >> 7, r = (idx >> 5) & 3, w = idx & 31;
        *(uint32_t*)(sm + (b ? OFF_B1 : OFF_B0) + (172 + r) * BSTR + w * 4) = 0;
    }
    __syncthreads();

    const float scale = rsqrtf((float)NROW);
    const int stride = gridDim.x;

    // ---- warp tile: wj 0..5 (32 j), wm 0..1 (units 4wm..4wm+3) ----
    const int wj = warp >> 1, wm = warp & 1;
    uint32_t a_frag[2][11][4];
    #pragma unroll
    for (int jt2 = 0; jt2 < 2; jt2++) {
        uint32_t a_addr = sbase
            + (uint32_t)((wj * 32 + jt2 * 16) + (lane & 7) + ((lane >> 3) & 1) * 8) * ASTR
            + (uint32_t)((lane >> 4) * 16);
        #pragma unroll
        for (int kt = 0; kt < 11; kt++)
            ldsm_x4(a_frag[jt2][kt], a_addr + kt * 32);
    }

    // B ldsm lane address (swizzled): row r_part = lane&15, unit u0 = (lane>>4)+4wm
    const int r_part = lane & 15;
    const int sswz = (r_part >> 1) & 3;
    const uint32_t b_lane_off =
        (uint32_t)(r_part * BSTR + ((((lane >> 4) + 4 * wm) ^ sswz) * 16));

    const int eq = lane & 3, er = lane >> 2;
    // epilogue m remap: unit t = 4wm+n holds m {4t..4t+3, 32+4t..+3}
    int m_base[4];
    #pragma unroll
    for (int n = 0; n < 4; n++) {
        int t = 4 * wm + n;
        m_base[n] = (eq < 2) ? (4 * t + 2 * eq) : (32 + 4 * t + 2 * (eq - 2));
    }

    const uint32_t xoff = (uint32_t)(g * 64 + tg * 4);

    int row0 = blockIdx.x;
    if (row0 < rows) {
        const float* xr = x + (size_t)row0 * NROW;
        #pragma unroll
        for (int p = 0; p < 4; p++) {
            int q = warp + 12 * p;
            if (q < NQUAD) {
                const float* b = xr + q * 256 + xoff;
                bfly8_store(*(const float4*)b, *(const float4*)(b + 32),
                            sm + OFF_B0, 4 * q + g, tg, scale);
            }
        }
    }
    __syncthreads();

    int buf = 0;
    for (int row = row0; row < rows; row += stride) {
        const int nxt = row + stride;
        const bool have_nxt = nxt < rows;
        char* bnext = sm + (buf ? OFF_B0 : OFF_B1);

        // -- prefetch next row's quads (retire under GEMM) --
        float4 pfl[4], pfh[4];
        if (have_nxt) {
            const float* xn = x + (size_t)nxt * NROW;
            #pragma unroll
            for (int p = 0; p < 4; p++) {
                int q = warp + 12 * p;
                if (q < NQUAD) {
                    const float* b = xn + q * 256 + xoff;
                    pfl[p] = *(const float4*)b;
                    pfh[p] = *(const float4*)(b + 32);
                }
            }
        }

        // -------- GEMM row i --------
        uint32_t bbase = sbase + (buf ? OFF_B1 : OFF_B0) + b_lane_off;
        float acc[2][4][4];
        #pragma unroll
        for (int jt2 = 0; jt2 < 2; jt2++)
            #pragma unroll
            for (int n = 0; n < 4; n++)
                acc[jt2][n][0] = acc[jt2][n][1] = acc[jt2][n][2] = acc[jt2][n][3] = 0.f;

        #pragma unroll
        for (int kt = 0; kt < 11; kt++) {
            uint32_t bk = bbase + (uint32_t)(kt * 16 * BSTR);
            uint32_t b0[4], b1[4];
            ldsm_x4t(b0, bk);          // units 4wm+0, 4wm+1
            ldsm_x4t(b1, bk ^ 32);     // units 4wm+2, 4wm+3  (unit XOR 2)
            #pragma unroll
            for (int jt2 = 0; jt2 < 2; jt2++) {
                mma_f16(acc[jt2][0], a_frag[jt2][kt], b0[0], b0[1]);
                mma_f16(acc[jt2][1], a_frag[jt2][kt], b0[2], b0[3]);
                mma_f16(acc[jt2][2], a_frag[jt2][kt], b1[0], b1[1]);
                mma_f16(acc[jt2][3], a_frag[jt2][kt], b1[2], b1[3]);
            }
        }

        // -- butterfly next row FIRST (critical path: STS -> barrier) --
        if (have_nxt) {
            #pragma unroll
            for (int p = 0; p < 4; p++) {
                int q = warp + 12 * p;
                if (q < NQUAD)
                    bfly8_store(pfl[p], pfh[p], bnext, 4 * q + g, tg, scale);
            }
        }

        // -------- epilogue: store 32j x 32m patch (remapped m) --------
        {
            float* orow = out + (size_t)row * NROW;
            #pragma unroll
            for (int jt2 = 0; jt2 < 2; jt2++) {
                int j1 = wj * 32 + jt2 * 16 + er;
                int j2 = j1 + 8;
                if (j1 < KDIM) {
                    float* o1 = orow + j1 * MDIM;
                    #pragma unroll
                    for (int n = 0; n < 4; n++)
                        *(float2*)(o1 + m_base[n]) = make_float2(acc[jt2][n][0], acc[jt2][n][1]);
                }
                if (j2 < KDIM) {
                    float* o2 = orow + j2 * MDIM;
                    #pragma unroll
                    for (int n = 0; n < 4; n++)
                        *(float2*)(o2 + m_base[n]) = make_float2(acc[jt2][n][2], acc[jt2][n][3]);
                }
            }
        }
        buf ^= 1;
        __syncthreads();
    }
}

extern "C" void kernel_launch(void* const* d_in, const int* in_sizes, int n_in,
                              void* d_out, int out_size) {
    const float* x   = (const float*)d_in[0];
    const float* had = (const float*)d_in[1];
    float* out = (float*)d_out;
    int rows = in_sizes[0] / NROW;

    cudaFuncSetAttribute(onl_had_r11_kernel,
                         cudaFuncAttributeMaxDynamicSharedMemorySize, SMEM_DYN);
    int grid = rows < 152 ? rows : 152;
    onl_had_r11_kernel<<<grid, NT, SMEM_DYN>>>(x, had, out, rows);
}

// round 12
// speedup vs baseline: 1.1688x; 1.1688x over previous
#include <cuda_runtime.h>
#include <cuda_fp16.h>
#include <cstdint>

// OnlineHadamard round 12: r10 GEMM/layout verbatim; FHT element mapping
// changed to m = 8*tg..8*tg+7 so the store is ONE conflict-free STS.128.
// (In-thread butterfly distances 1,2,4; shfl xor 1,2,4 -> distances 8,16,32.)

#define KDIM 172
#define MDIM 64
#define NROW 11008
#define NT 384

#define ASTR 368
#define BSTR 144
#define A_BYTES (192 * ASTR)
#define B_BYTES (176 * BSTR)
#define OFF_B0  (A_BYTES)
#define OFF_B1  (A_BYTES + B_BYTES)
#define SMEM_DYN (A_BYTES + 2 * B_BYTES)   // 121344
#define NQUAD 43

__device__ __forceinline__ uint32_t smem_u32(const void* p) {
    uint32_t a;
    asm("{ .reg .u64 t; cvta.to.shared.u64 t, %1; cvt.u32.u64 %0, t; }" : "=r"(a) : "l"(p));
    return a;
}
__device__ __forceinline__ uint32_t h2_u32(__half2 h) {
    uint32_t u;
    *(__half2*)&u = h;
    return u;
}
__device__ __forceinline__ void ldsm_x4(uint32_t* r, uint32_t addr) {
    asm volatile("ldmatrix.sync.aligned.m8n8.x4.shared.b16 {%0,%1,%2,%3}, [%4];"
                 : "=r"(r[0]), "=r"(r[1]), "=r"(r[2]), "=r"(r[3]) : "r"(addr));
}
__device__ __forceinline__ void ldsm_x4t(uint32_t* r, uint32_t addr) {
    asm volatile("ldmatrix.sync.aligned.m8n8.x4.trans.shared.b16 {%0,%1,%2,%3}, [%4];"
                 : "=r"(r[0]), "=r"(r[1]), "=r"(r[2]), "=r"(r[3]) : "r"(addr));
}
__device__ __forceinline__ void mma_f16(float* c, const uint32_t* a, uint32_t b0, uint32_t b1) {
    asm volatile("mma.sync.aligned.m16n8k16.row.col.f32.f16.f16.f32 "
                 "{%0,%1,%2,%3}, {%4,%5,%6,%7}, {%8,%9}, {%0,%1,%2,%3};"
                 : "+f"(c[0]), "+f"(c[1]), "+f"(c[2]), "+f"(c[3])
                 : "r"(a[0]), "r"(a[1]), "r"(a[2]), "r"(a[3]), "r"(b0), "r"(b1));
}

// FHT64, thread holds m = 8*tg + i (i<4 in lo, i>=4 in hi, contiguous 8).
// In-thread: distances 1,2,4. Shfl xor s (s=1,2,4): distances 8s.
// Store: one STS.128 of the thread's 8 halves at c*BSTR + tg*16 (m-order layout).
__device__ __forceinline__ void bfly8_store(float4 lo, float4 hi, char* bbuf,
                                            int c, int tg, float scale) {
    float v[8] = {lo.x, lo.y, lo.z, lo.w, hi.x, hi.y, hi.z, hi.w};
    float t;
    // distance 1
    #pragma unroll
    for (int g2 = 0; g2 < 8; g2 += 2) { t = v[g2]; v[g2] = t + v[g2+1]; v[g2+1] = t - v[g2+1]; }
    // distance 2
    #pragma unroll
    for (int b = 0; b < 8; b += 4)
        #pragma unroll
        for (int i = 0; i < 2; i++) {
            t = v[b+i]; v[b+i] = t + v[b+i+2]; v[b+i+2] = t - v[b+i+2];
        }
    // distance 4
    #pragma unroll
    for (int i = 0; i < 4; i++) { t = v[i]; v[i] = t + v[i+4]; v[i+4] = t - v[i+4]; }
    // distances 8, 16, 32 -> lane xor 1, 2, 4 (within 8-lane groups)
    #pragma unroll
    for (int s = 1; s <= 4; s <<= 1) {
        bool up = (tg & s) != 0;
        #pragma unroll
        for (int i = 0; i < 8; i++) {
            float q = __shfl_xor_sync(0xffffffffu, v[i], s);
            v[i] = up ? (q - v[i]) : (v[i] + q);
        }
    }
    uint32_t h01 = h2_u32(__floats2half2_rn(v[0]*scale, v[1]*scale));
    uint32_t h23 = h2_u32(__floats2half2_rn(v[2]*scale, v[3]*scale));
    uint32_t h45 = h2_u32(__floats2half2_rn(v[4]*scale, v[5]*scale));
    uint32_t h67 = h2_u32(__floats2half2_rn(v[6]*scale, v[7]*scale));
    *(uint4*)(bbuf + c * BSTR + tg * 16) = make_uint4(h01, h23, h45, h67);
}

__global__ __launch_bounds__(NT, 1)
void onl_had_r12_kernel(const float* __restrict__ x,
                        const float* __restrict__ had,
                        float* __restrict__ out, int rows)
{
    extern __shared__ char sm[];
    const uint32_t sbase = smem_u32(sm);
    const int tid = threadIdx.x, lane = tid & 31, warp = tid >> 5;
    const int tg = lane & 7, g = lane >> 3;

    // ---- one-time: A = had (fp16), zero-padded to 192x176 ----
    for (int idx = tid; idx < 192 * 176; idx += NT) {
        int j = idx / 176, k = idx - j * 176;
        float v = (j < KDIM && k < KDIM) ? had[j * KDIM + k] : 0.0f;
        *(__half*)(sm + j * ASTR + 2 * k) = __float2half_rn(v);
    }
    for (int idx = tid; idx < 2 * 4 * 64; idx += NT) {
        int b = idx >> 8, r = (idx >> 6) & 3, m = idx & 63;
        char* p = sm + (b ? OFF_B1 : OFF_B0) + (172 + r) * BSTR;
        *(__half*)(p + 2 * m) = __float2half_rn(0.0f);
    }
    __syncthreads();

    const float scale = rsqrtf((float)NROW);
    const int stride = gridDim.x;

    // ---- warp tile: wj 0..5 (32 j), wm 0..1 (32 m) ----  (r10 verbatim)
    const int wj = warp >> 1, wm = warp & 1;
    uint32_t a_frag[2][11][4];
    #pragma unroll
    for (int jt2 = 0; jt2 < 2; jt2++) {
        uint32_t a_addr = sbase
            + (uint32_t)((wj * 32 + jt2 * 16) + (lane & 7) + ((lane >> 3) & 1) * 8) * ASTR
            + (uint32_t)((lane >> 4) * 16);
        #pragma unroll
        for (int kt = 0; kt < 11; kt++)
            ldsm_x4(a_frag[jt2][kt], a_addr + kt * 32);
    }

    uint32_t b_lane_off = (uint32_t)((lane & 15) * BSTR + (lane >> 4) * 16 + wm * 64);
    const int eq = lane & 3, er = lane >> 2;

    // FHT: thread loads two adjacent float4 at m = 8*tg (chunk c = 4q+g)
    const uint32_t xoff = (uint32_t)(g * 64 + tg * 8);

    int row0 = blockIdx.x;
    if (row0 < rows) {
        const float* xr = x + (size_t)row0 * NROW;
        #pragma unroll
        for (int p = 0; p < 4; p++) {
            int q = warp + 12 * p;
            if (q < NQUAD) {
                const float* b = xr + q * 256 + xoff;
                bfly8_store(*(const float4*)b, *(const float4*)(b + 4),
                            sm + OFF_B0, 4 * q + g, tg, scale);
            }
        }
    }
    __syncthreads();

    int buf = 0;
    for (int row = row0; row < rows; row += stride) {
        const int nxt = row + stride;
        const bool have_nxt = nxt < rows;
        char* bnext = sm + (buf ? OFF_B0 : OFF_B1);

        // -- prefetch next row's quads (retire under GEMM) --
        float4 pfl[4], pfh[4];
        if (have_nxt) {
            const float* xn = x + (size_t)nxt * NROW;
            #pragma unroll
            for (int p = 0; p < 4; p++) {
                int q = warp + 12 * p;
                if (q < NQUAD) {
                    const float* b = xn + q * 256 + xoff;
                    pfl[p] = *(const float4*)b;
                    pfh[p] = *(const float4*)(b + 4);
                }
            }
        }

        // -------- GEMM row i: 32j x 32m per warp (r10 verbatim) --------
        uint32_t bbase = sbase + (buf ? OFF_B1 : OFF_B0) + b_lane_off;
        float acc[2][4][4];
        #pragma unroll
        for (int jt2 = 0; jt2 < 2; jt2++)
            #pragma unroll
            for (int n = 0; n < 4; n++)
                acc[jt2][n][0] = acc[jt2][n][1] = acc[jt2][n][2] = acc[jt2][n][3] = 0.f;

        #pragma unroll
        for (int kt = 0; kt < 11; kt++) {
            uint32_t bk = bbase + (uint32_t)(kt * 16 * BSTR);
            uint32_t b0[4], b1[4];
            ldsm_x4t(b0, bk);
            ldsm_x4t(b1, bk + 32);
            #pragma unroll
            for (int jt2 = 0; jt2 < 2; jt2++) {
                mma_f16(acc[jt2][0], a_frag[jt2][kt], b0[0], b0[1]);
                mma_f16(acc[jt2][1], a_frag[jt2][kt], b0[2], b0[3]);
                mma_f16(acc[jt2][2], a_frag[jt2][kt], b1[0], b1[1]);
                mma_f16(acc[jt2][3], a_frag[jt2][kt], b1[2], b1[3]);
            }
        }

        // -- butterfly next row first (STS -> barrier is the critical path) --
        if (have_nxt) {
            #pragma unroll
            for (int p = 0; p < 4; p++) {
                int q = warp + 12 * p;
                if (q < NQUAD)
                    bfly8_store(pfl[p], pfh[p], bnext, 4 * q + g, tg, scale);
            }
        }

        // -------- epilogue: store 32j x 32m patch (r10 verbatim, coalesced) --------
        {
            float* orow = out + (size_t)row * NROW + wm * 32 + eq * 2;
            #pragma unroll
            for (int jt2 = 0; jt2 < 2; jt2++) {
                int j1 = wj * 32 + jt2 * 16 + er;
                int j2 = j1 + 8;
                if (j1 < KDIM) {
                    float* o1 = orow + j1 * MDIM;
                    #pragma unroll
                    for (int n = 0; n < 4; n++)
                        *(float2*)(o1 + n * 8) = make_float2(acc[jt2][n][0], acc[jt2][n][1]);
                }
                if (j2 < KDIM) {
                    float* o2 = orow + j2 * MDIM;
                    #pragma unroll
                    for (int n = 0; n < 4; n++)
                        *(float2*)(o2 + n * 8) = make_float2(acc[jt2][n][2], acc[jt2][n][3]);
                }
            }
        }
        buf ^= 1;
        __syncthreads();
    }
}

extern "C" void kernel_launch(void* const* d_in, const int* in_sizes, int n_in,
                              void* d_out, int out_size) {
    const float* x   = (const float*)d_in[0];
    const float* had = (const float*)d_in[1];
    float* out = (float*)d_out;
    int rows = in_sizes[0] / NROW;

    cudaFuncSetAttribute(onl_had_r12_kernel,
                         cudaFuncAttributeMaxDynamicSharedMemorySize, SMEM_DYN);
    int grid = rows < 152 ? rows : 152;
    onl_had_r12_kernel<<<grid, NT, SMEM_DYN>>>(x, had, out, rows);
}

// round 13
// speedup vs baseline: 1.3008x; 1.1129x over previous
#include <cuda_runtime.h>
#include <cuda_fp16.h>
#include <cstdint>

// OnlineHadamard round 13: r10 mappings verbatim + (a) XOR-swizzled B placement
// (BSTR=192, unit u at u ^ ((k>>1)&3)) killing STS bank conflicts, and
// (b) two rows per barrier with 4 B buffers.

#define KDIM 172
#define MDIM 64
#define NROW 11008
#define NT 384

#define ASTR 368
#define BSTR 192
#define A_BYTES (192 * ASTR)              // 70656
#define B_BYTES (176 * BSTR)              // 33792 per buffer
#define OFF_B(i) (A_BYTES + (i) * B_BYTES)
#define SMEM_DYN (A_BYTES + 4 * B_BYTES)  // 205824
#define NQUAD 43

__device__ __forceinline__ uint32_t smem_u32(const void* p) {
    uint32_t a;
    asm("{ .reg .u64 t; cvta.to.shared.u64 t, %1; cvt.u32.u64 %0, t; }" : "=r"(a) : "l"(p));
    return a;
}
__device__ __forceinline__ uint32_t h2_u32(__half2 h) {
    uint32_t u;
    *(__half2*)&u = h;
    return u;
}
__device__ __forceinline__ void ldsm_x4(uint32_t* r, uint32_t addr) {
    asm volatile("ldmatrix.sync.aligned.m8n8.x4.shared.b16 {%0,%1,%2,%3}, [%4];"
                 : "=r"(r[0]), "=r"(r[1]), "=r"(r[2]), "=r"(r[3]) : "r"(addr));
}
__device__ __forceinline__ void ldsm_x4t(uint32_t* r, uint32_t addr) {
    asm volatile("ldmatrix.sync.aligned.m8n8.x4.trans.shared.b16 {%0,%1,%2,%3}, [%4];"
                 : "=r"(r[0]), "=r"(r[1]), "=r"(r[2]), "=r"(r[3]) : "r"(addr));
}
__device__ __forceinline__ void mma_f16(float* c, const uint32_t* a, uint32_t b0, uint32_t b1) {
    asm volatile("mma.sync.aligned.m16n8k16.row.col.f32.f16.f16.f32 "
                 "{%0,%1,%2,%3}, {%4,%5,%6,%7}, {%8,%9}, {%0,%1,%2,%3};"
                 : "+f"(c[0]), "+f"(c[1]), "+f"(c[2]), "+f"(c[3])
                 : "r"(a[0]), "r"(a[1]), "r"(a[2]), "r"(a[3]), "r"(b0), "r"(b1));
}

// r10 butterfly verbatim (8 elems/thread, m = {4tg..4tg+3, 32+4tg..32+4tg+3});
// only the STORE ADDRESS is swizzled: unit (tg>>1)^((c>>1)&3), +64B for hi half.
__device__ __forceinline__ void bfly8_store(float4 lo, float4 hi, char* bbuf,
                                            int c, int tg, float scale) {
    float v[8] = {lo.x, lo.y, lo.z, lo.w, hi.x, hi.y, hi.z, hi.w};
    float t;
    #pragma unroll
    for (int i = 0; i < 4; i++) { t = v[i]; v[i] = t + v[i+4]; v[i+4] = t - v[i+4]; }
    #pragma unroll
    for (int g2 = 0; g2 < 8; g2 += 2) { t = v[g2]; v[g2] = t + v[g2+1]; v[g2+1] = t - v[g2+1]; }
    #pragma unroll
    for (int b = 0; b < 8; b += 4)
        #pragma unroll
        for (int i = 0; i < 2; i++) {
            t = v[b+i]; v[b+i] = t + v[b+i+2]; v[b+i+2] = t - v[b+i+2];
        }
    #pragma unroll
    for (int s = 1; s <= 4; s <<= 1) {
        bool up = (tg & s) != 0;
        #pragma unroll
        for (int i = 0; i < 8; i++) {
            float q = __shfl_xor_sync(0xffffffffu, v[i], s);
            v[i] = up ? (q - v[i]) : (v[i] + q);
        }
    }
    uint32_t h01 = h2_u32(__floats2half2_rn(v[0]*scale, v[1]*scale));
    uint32_t h23 = h2_u32(__floats2half2_rn(v[2]*scale, v[3]*scale));
    uint32_t h45 = h2_u32(__floats2half2_rn(v[4]*scale, v[5]*scale));
    uint32_t h67 = h2_u32(__floats2half2_rn(v[6]*scale, v[7]*scale));
    uint32_t a1 = (uint32_t)(c * BSTR + (((tg >> 1) ^ ((c >> 1) & 3)) * 16) + (tg & 1) * 8);
    *(uint2*)(bbuf + a1)      = make_uint2(h01, h23);   // m 4tg..4tg+3
    *(uint2*)(bbuf + a1 + 64) = make_uint2(h45, h67);   // m 32+4tg.. (+4 units)
}

__global__ __launch_bounds__(NT, 1)
void onl_had_r13_kernel(const float* __restrict__ x,
                        const float* __restrict__ had,
                        float* __restrict__ out, int rows)
{
    extern __shared__ char sm[];
    const uint32_t sbase = smem_u32(sm);
    const int tid = threadIdx.x, lane = tid & 31, warp = tid >> 5;
    const int tg = lane & 7, g = lane >> 3;

    // ---- one-time: A = had (fp16), zero-padded to 192x176 ----
    for (int idx = tid; idx < 192 * 176; idx += NT) {
        int j = idx / 176, k = idx - j * 176;
        float v = (j < KDIM && k < KDIM) ? had[j * KDIM + k] : 0.0f;
        *(__half*)(sm + j * ASTR + 2 * k) = __float2half_rn(v);
    }
    // zero data units (128B) of B pad rows 172..175, all 4 buffers
    for (int idx = tid; idx < 4 * 4 * 32; idx += NT) {
        int b = idx >> 7, r = (idx >> 5) & 3, w = idx & 31;
        *(uint32_t*)(sm + OFF_B(b) + (172 + r) * BSTR + w * 4) = 0;
    }
    __syncthreads();

    const float scale = rsqrtf((float)NROW);
    const int s1 = gridDim.x, s2 = 2 * s1;

    // ---- warp tile: wj 0..5 (32 j), wm 0..1 (32 m) ----  (r10 verbatim)
    const int wj = warp >> 1, wm = warp & 1;
    uint32_t a_frag[2][11][4];
    #pragma unroll
    for (int jt2 = 0; jt2 < 2; jt2++) {
        uint32_t a_addr = sbase
            + (uint32_t)((wj * 32 + jt2 * 16) + (lane & 7) + ((lane >> 3) & 1) * 8) * ASTR
            + (uint32_t)((lane >> 4) * 16);
        #pragma unroll
        for (int kt = 0; kt < 11; kt++)
            ldsm_x4(a_frag[jt2][kt], a_addr + kt * 32);
    }

    // B ldsm lane offset with folded swizzle; second half = addr ^ 32
    const int r_part = lane & 15;
    const int u0 = 4 * wm + (lane >> 4);                 // bit1 == 0
    const uint32_t b_lane_off =
        (uint32_t)(r_part * BSTR + (((u0 ^ ((r_part >> 1) & 3))) * 16));
    const int eq = lane & 3, er = lane >> 2;

    const uint32_t xoff = (uint32_t)(g * 64 + tg * 4);   // r10 LDG mapping

    // GEMM + epilogue for one row from buffer `bbuf` (r10 verbatim inner loop)
    auto gemm_epi = [&](int row, const char* bbuf) {
        uint32_t bbase = sbase + (uint32_t)(bbuf - sm) + b_lane_off;
        float acc[2][4][4];
        #pragma unroll
        for (int jt2 = 0; jt2 < 2; jt2++)
            #pragma unroll
            for (int n = 0; n < 4; n++)
                acc[jt2][n][0] = acc[jt2][n][1] = acc[jt2][n][2] = acc[jt2][n][3] = 0.f;
        #pragma unroll
        for (int kt = 0; kt < 11; kt++) {
            uint32_t bk = bbase + (uint32_t)(kt * 16 * BSTR);
            uint32_t b0[4], b1[4];
            ldsm_x4t(b0, bk);
            ldsm_x4t(b1, bk ^ 32);
            #pragma unroll
            for (int jt2 = 0; jt2 < 2; jt2++) {
                mma_f16(acc[jt2][0], a_frag[jt2][kt], b0[0], b0[1]);
                mma_f16(acc[jt2][1], a_frag[jt2][kt], b0[2], b0[3]);
                mma_f16(acc[jt2][2], a_frag[jt2][kt], b1[0], b1[1]);
                mma_f16(acc[jt2][3], a_frag[jt2][kt], b1[2], b1[3]);
            }
        }
        float* orow = out + (size_t)row * NROW + wm * 32 + eq * 2;
        #pragma unroll
        for (int jt2 = 0; jt2 < 2; jt2++) {
            int j1 = wj * 32 + jt2 * 16 + er;
            int j2 = j1 + 8;
            if (j1 < KDIM) {
                float* o1 = orow + j1 * MDIM;
                #pragma unroll
                for (int n = 0; n < 4; n++)
                    *(float2*)(o1 + n * 8) = make_float2(acc[jt2][n][0], acc[jt2][n][1]);
            }
            if (j2 < KDIM) {
                float* o2 = orow + j2 * MDIM;
                #pragma unroll
                for (int n = 0; n < 4; n++)
                    *(float2*)(o2 + n * 8) = make_float2(acc[jt2][n][2], acc[jt2][n][3]);
            }
        }
    };

    auto fht_from_gmem = [&](int row, char* bbuf) {
        const float* xr = x + (size_t)row * NROW;
        #pragma unroll
        for (int p = 0; p < 4; p++) {
            int q = warp + 12 * p;
            if (q < NQUAD) {
                const float* b = xr + q * 256 + xoff;
                bfly8_store(*(const float4*)b, *(const float4*)(b + 32),
                            bbuf, 4 * q + g, tg, scale);
            }
        }
    };

    // ---- prologue: rows row0, row0+s1 into buffers 0, 1 ----
    int row0 = blockIdx.x;
    if (row0 < rows)      fht_from_gmem(row0, sm + OFF_B(0));
    if (row0 + s1 < rows) fht_from_gmem(row0 + s1, sm + OFF_B(1));
    __syncthreads();

    int pb = 0;   // pair buffer base: 0 or 2
    for (int ra = row0; ra < rows; ra += s2) {
        const int rb = ra + s1, rc = ra + s2, rd = ra + 3 * s1;
        char* bufC = sm + OFF_B(pb ^ 2);
        char* bufD = sm + OFF_B((pb ^ 2) + 1);

        // prefetch rc, GEMM+epi ra, butterfly rc
        float4 pfl[4], pfh[4];
        if (rc < rows) {
            const float* xn = x + (size_t)rc * NROW;
            #pragma unroll
            for (int p = 0; p < 4; p++) {
                int q = warp + 12 * p;
                if (q < NQUAD) {
                    const float* b = xn + q * 256 + xoff;
                    pfl[p] = *(const float4*)b;
                    pfh[p] = *(const float4*)(b + 32);
                }
            }
        }
        gemm_epi(ra, sm + OFF_B(pb));
        if (rc < rows) {
            #pragma unroll
            for (int p = 0; p < 4; p++) {
                int q = warp + 12 * p;
                if (q < NQUAD)
                    bfly8_store(pfl[p], pfh[p], bufC, 4 * q + g, tg, scale);
            }
        }

        // prefetch rd, GEMM+epi rb, butterfly rd
        if (rd < rows) {
            const float* xn = x + (size_t)rd * NROW;
            #pragma unroll
            for (int p = 0; p < 4; p++) {
                int q = warp + 12 * p;
                if (q < NQUAD) {
                    const float* b = xn + q * 256 + xoff;
                    pfl[p] = *(const float4*)b;
                    pfh[p] = *(const float4*)(b + 32);
                }
            }
        }
        if (rb < rows) gemm_epi(rb, sm + OFF_B(pb + 1));
        if (rd < rows) {
            #pragma unroll
            for (int p = 0; p < 4; p++) {
                int q = warp + 12 * p;
                if (q < NQUAD)
                    bfly8_store(pfl[p], pfh[p], bufD, 4 * q + g, tg, scale);
            }
        }

        pb ^= 2;
        __syncthreads();
    }
}

extern "C" void kernel_launch(void* const* d_in, const int* in_sizes, int n_in,
                              void* d_out, int out_size) {
    const float* x   = (const float*)d_in[0];
    const float* had = (const float*)d_in[1];
    float* out = (float*)d_out;
    int rows = in_sizes[0] / NROW;

    cudaFuncSetAttribute(onl_had_r13_kernel,
                         cudaFuncAttributeMaxDynamicSharedMemorySize, SMEM_DYN);
    int grid = rows < 152 ? rows : 152;
    onl_had_r13_kernel<<<grid, NT, SMEM_DYN>>>(x, had, out, rows);
}